// round 15
// baseline (speedup 1.0000x reference)
#include <cuda_runtime.h>
#include <cuda_fp16.h>
#include <stdint.h>

#define TT   8192
#define DDim 2048
#define FFD  8192
#define NE   2
#define PADT 8448      // 66*128
#define NT   66
#define STAGE12 98304  // [A-lo|A-hi|Bg-lo|Bg-hi|Bu-lo|Bu-hi] 6x16KB
#define STAGE3  65536  // [A-lo|A-hi|B-lo|B-hi] 4x16KB
#define SMEM12 (2*STAGE12)
#define SMEM3  (2*STAGE3)

// ---------------- scratch ----------------
__device__ __align__(256) __half g_Xh[(size_t)PADT*DDim];
__device__ __align__(256) __half g_Wg[(size_t)NE*FFD*DDim];
__device__ __align__(256) __half g_Wu[(size_t)NE*FFD*DDim];
__device__ __align__(256) __half g_Wd[(size_t)NE*DDim*FFD];
__device__ __align__(256) __half g_H[(size_t)PADT*FFD];
__device__ int   g_sel[TT];
__device__ float g_topw[TT];
__device__ int   g_tok[PADT];
__device__ int   g_cnt[2];
__device__ int   g_pos[2];

// ---------------- helpers ----------------
__device__ __forceinline__ void cp16(uint32_t saddr, const void* gaddr) {
    asm volatile("cp.async.cg.shared.global [%0], [%1], 16;\n"
                 :: "r"(saddr), "l"(gaddr) : "memory");
}
__device__ __forceinline__ void ldsm4(uint32_t* r, uint32_t addr) {
    asm volatile("ldmatrix.sync.aligned.m8n8.x4.shared.b16 {%0,%1,%2,%3}, [%4];\n"
                 : "=r"(r[0]), "=r"(r[1]), "=r"(r[2]), "=r"(r[3])
                 : "r"(addr) : "memory");
}
__device__ __forceinline__ void mma_f16(float* c, const uint32_t* a, const uint32_t* b) {
    asm volatile("mma.sync.aligned.m16n8k16.row.col.f32.f16.f16.f32 "
                 "{%0,%1,%2,%3}, {%4,%5,%6,%7}, {%8,%9}, {%0,%1,%2,%3};\n"
                 : "+f"(c[0]), "+f"(c[1]), "+f"(c[2]), "+f"(c[3])
                 : "r"(a[0]), "r"(a[1]), "r"(a[2]), "r"(a[3]),
                   "r"(b[0]), "r"(b[1]));
}
__device__ __forceinline__ uint32_t pack_h2(float a, float b) {
    __half2 h = __halves2half2(__float2half(a), __float2half(b));
    return *(uint32_t*)&h;
}

// ---------------- small kernels ----------------
__global__ void init_kernel() {
    int i = blockIdx.x * blockDim.x + threadIdx.x;
    if (i < PADT) g_tok[i] = -1;
    if (i == 0) { g_cnt[0] = 0; g_cnt[1] = 0; g_pos[0] = 0; g_pos[1] = 0; }
}

__global__ void router_kernel(const float* __restrict__ x, const float* __restrict__ gw) {
    int gt = blockIdx.x * blockDim.x + threadIdx.x;
    int t = gt >> 5, lane = gt & 31;
    if (t >= TT) return;
    const float* xr = x + (size_t)t * DDim;
    float a0 = 0.f, a1 = 0.f;
    for (int d = lane; d < DDim; d += 32) {
        float xv = xr[d];
        a0 += xv * gw[d];
        a1 += xv * gw[DDim + d];
    }
#pragma unroll
    for (int o = 16; o; o >>= 1) {
        a0 += __shfl_xor_sync(0xffffffffu, a0, o);
        a1 += __shfl_xor_sync(0xffffffffu, a1, o);
    }
    if (lane == 0) {
        int sel = (a0 >= a1) ? 0 : 1;
        float m = fmaxf(a0, a1);
        float e0 = expf(a0 - m), e1 = expf(a1 - m);
        float p = ((sel == 0) ? e0 : e1) / (e0 + e1);
        g_sel[t] = sel;
        g_topw[t] = p;
        atomicAdd(&g_cnt[sel], 1);
    }
}

// fused assign + gather: one warp per token claims a slot, copies/converts the row.
__global__ void assign_gather_kernel(const float* __restrict__ x) {
    int gt = blockIdx.x * blockDim.x + threadIdx.x;
    int t = gt >> 5, lane = gt & 31;
    if (t >= TT) return;
    int slot = 0;
    if (lane == 0) {
        int sel = g_sel[t];
        int base = sel ? (((g_cnt[0] + 127) >> 7) << 7) : 0;
        int p = atomicAdd(&g_pos[sel], 1);
        slot = base + p;
        g_tok[slot] = t;
    }
    slot = __shfl_sync(0xffffffffu, slot, 0);
    const float4* xr = (const float4*)(x + (size_t)t * DDim);
    __half* dst = g_Xh + (size_t)slot * DDim;
#pragma unroll 4
    for (int c = lane; c < DDim / 4; c += 32) {
        float4 v = __ldcs(xr + c);
        uint2 o;
        o.x = pack_h2(v.x, v.y);
        o.y = pack_h2(v.z, v.w);
        *(uint2*)(dst + c * 4) = o;
    }
}

// streaming fp32->fp16 weight conversion
__global__ void __launch_bounds__(512)
wconv_gu_kernel(const float* __restrict__ wg, const float* __restrict__ wu) {
    const size_t n16 = (size_t)NE * FFD * DDim / 16;
    size_t idx = (size_t)blockIdx.x * blockDim.x + threadIdx.x;
    if (idx >= n16) return;
    const float* src = (blockIdx.y == 0) ? wg : wu;
    __half* dst = (blockIdx.y == 0) ? g_Wg : g_Wu;
    const float4* s4 = (const float4*)src + idx * 4;
    float4 v0 = __ldcs(s4);
    float4 v1 = __ldcs(s4 + 1);
    float4 v2 = __ldcs(s4 + 2);
    float4 v3 = __ldcs(s4 + 3);
    uint4 o0, o1;
    o0.x = pack_h2(v0.x, v0.y); o0.y = pack_h2(v0.z, v0.w);
    o0.z = pack_h2(v1.x, v1.y); o0.w = pack_h2(v1.z, v1.w);
    o1.x = pack_h2(v2.x, v2.y); o1.y = pack_h2(v2.z, v2.w);
    o1.z = pack_h2(v3.x, v3.y); o1.w = pack_h2(v3.z, v3.w);
    __stcs((uint4*)(dst + idx * 16), o0);
    __stcs((uint4*)(dst + idx * 16) + 1, o1);
}

__global__ void __launch_bounds__(512)
wconv_d_kernel(const float* __restrict__ wd) {
    const size_t n16 = (size_t)NE * FFD * DDim / 16;
    size_t idx = (size_t)blockIdx.x * blockDim.x + threadIdx.x;
    if (idx >= n16) return;
    const float4* s4 = (const float4*)wd + idx * 4;
    float4 v0 = __ldcs(s4);
    float4 v1 = __ldcs(s4 + 1);
    float4 v2 = __ldcs(s4 + 2);
    float4 v3 = __ldcs(s4 + 3);
    uint4 o0, o1;
    o0.x = pack_h2(v0.x, v0.y); o0.y = pack_h2(v0.z, v0.w);
    o0.z = pack_h2(v1.x, v1.y); o0.w = pack_h2(v1.z, v1.w);
    o1.x = pack_h2(v2.x, v2.y); o1.y = pack_h2(v2.z, v2.w);
    o1.z = pack_h2(v3.x, v3.y); o1.w = pack_h2(v3.z, v3.w);
    __stcs((uint4*)(g_Wd + idx * 16), o0);
    __stcs((uint4*)(g_Wd + idx * 16) + 1, o1);
}

// ============ fused gate+up GEMM: tile M128 x N128 x K128-slab (256 thr) ============
struct Frag12 { uint32_t a[4][4]; uint32_t g[4][2]; uint32_t u[4][2]; };

__device__ __forceinline__ void fetch12(Frag12& f, uint32_t sA, uint32_t sBg, uint32_t sBu,
                                        int k16, int wm, int wn,
                                        int lrA, int lcA, int lrB, int lcB) {
    uint32_t hi = (uint32_t)(k16 >> 2) << 14;
    int kk = k16 & 3;
#pragma unroll
    for (int m = 0; m < 4; ++m) {
        int row = wm * 64 + m * 16 + lrA;
        uint32_t off = hi + ((uint32_t)row << 7) + ((uint32_t)((kk * 2 + lcA) ^ (row & 7)) << 4);
        ldsm4(f.a[m], sA + off);
    }
#pragma unroll
    for (int p = 0; p < 2; ++p) {
        int row = wn * 32 + p * 16 + lrB;
        uint32_t off = hi + ((uint32_t)row << 7) + ((uint32_t)((kk * 2 + lcB) ^ (row & 7)) << 4);
        uint32_t r4[4];
        ldsm4(r4, sBg + off);
        f.g[2*p][0] = r4[0]; f.g[2*p][1] = r4[1]; f.g[2*p+1][0] = r4[2]; f.g[2*p+1][1] = r4[3];
        ldsm4(r4, sBu + off);
        f.u[2*p][0] = r4[0]; f.u[2*p][1] = r4[1]; f.u[2*p+1][0] = r4[2]; f.u[2*p+1][1] = r4[3];
    }
}

__device__ __forceinline__ void load_stage12(uint32_t sb, int tid, int k0,
                                             int row0, int bgrow) {
#pragma unroll
    for (int i = 0; i < 24; ++i) {
        int q = tid + (i << 8);
        int mat = q >> 10;
        int q10 = q & 1023;
        int r = q10 >> 3;
        int c = q10 & 7;
        uint32_t so = sb + ((uint32_t)mat << 14) + (r << 7) + ((c ^ (r & 7)) << 4);
        int kk = k0 + ((mat & 1) << 6) + (c << 3);
        int sel = mat >> 1;
        const __half* base = (sel == 0) ? (g_Xh + (size_t)(row0 + r) * DDim)
                           : (sel == 1) ? (g_Wg + (size_t)(bgrow + r) * DDim)
                                        : (g_Wu + (size_t)(bgrow + r) * DDim);
        cp16(so, base + kk);
    }
    asm volatile("cp.async.commit_group;\n" ::: "memory");
}

__global__ void __launch_bounds__(256, 1)
gemm12_kernel()
{
    int n0t = (g_cnt[0] + 127) >> 7, n1t = (g_cnt[1] + 127) >> 7;
    int tt = blockIdx.x;
    if (tt >= n0t + n1t) return;
    int expert = (tt < n0t) ? 0 : 1;
    int row0 = tt << 7;
    int col0 = blockIdx.y << 7;
    int bgrow = expert * FFD + col0;

    extern __shared__ char smem[];
    uint32_t sbase = (uint32_t)__cvta_generic_to_shared(smem);
    int tid = threadIdx.x, wid = tid >> 5, lane = tid & 31;
    int wm = wid & 1, wn = wid >> 1;

    int lrA = (lane & 7) + (((lane >> 3) & 1) << 3);
    int lcA = lane >> 4;
    int lrB = (lane & 7) + ((lane >> 4) << 3);
    int lcB = (lane >> 3) & 1;

    float ag[4][4][4], au[4][4][4];
#pragma unroll
    for (int m = 0; m < 4; ++m)
#pragma unroll
        for (int n = 0; n < 4; ++n)
#pragma unroll
            for (int i = 0; i < 4; ++i) { ag[m][n][i] = 0.f; au[m][n][i] = 0.f; }

    const int kTiles = DDim >> 7;             // 16
    load_stage12(sbase, tid, 0, row0, bgrow);
    Frag12 fr[2];

    for (int kt = 0; kt < kTiles; ++kt) {
        asm volatile("cp.async.wait_group 0;\n" ::: "memory");
        __syncthreads();
        uint32_t sb = sbase + (uint32_t)(kt & 1) * STAGE12;
        uint32_t sA = sb, sBg = sb + 32768, sBu = sb + 65536;

        fetch12(fr[0], sA, sBg, sBu, 0, wm, wn, lrA, lcA, lrB, lcB);
        if (kt + 1 < kTiles)
            load_stage12(sbase + (uint32_t)((kt + 1) & 1) * STAGE12, tid,
                         (kt + 1) << 7, row0, bgrow);
#pragma unroll
        for (int k16 = 0; k16 < 8; ++k16) {
            int cur = k16 & 1;
            if (k16 < 7)
                fetch12(fr[cur ^ 1], sA, sBg, sBu, k16 + 1, wm, wn, lrA, lcA, lrB, lcB);
#pragma unroll
            for (int m = 0; m < 4; ++m)
#pragma unroll
                for (int n = 0; n < 4; ++n) {
                    mma_f16(ag[m][n], fr[cur].a[m], fr[cur].g[n]);
                    mma_f16(au[m][n], fr[cur].a[m], fr[cur].u[n]);
                }
        }
    }

    // epilogue: h = silu(g) * u -> fp16 H
#pragma unroll
    for (int m = 0; m < 4; ++m) {
        int grow = row0 + wm * 64 + m * 16 + (lane >> 2);
#pragma unroll
        for (int n = 0; n < 4; ++n) {
            int gcol = col0 + wn * 32 + n * 8 + (lane & 3) * 2;
            float h0 = ag[m][n][0] * au[m][n][0] / (1.f + expf(-ag[m][n][0]));
            float h1 = ag[m][n][1] * au[m][n][1] / (1.f + expf(-ag[m][n][1]));
            float h2 = ag[m][n][2] * au[m][n][2] / (1.f + expf(-ag[m][n][2]));
            float h3 = ag[m][n][3] * au[m][n][3] / (1.f + expf(-ag[m][n][3]));
            *(uint32_t*)(g_H + (size_t)grow * FFD + gcol)       = pack_h2(h0, h1);
            *(uint32_t*)(g_H + (size_t)(grow + 8) * FFD + gcol) = pack_h2(h2, h3);
        }
    }
}

// ===== down GEMM: tile M128 x N128, 128 threads, warp 64x64 (MMA-bound) =====
struct Frag3 { uint32_t a[4][4]; uint32_t b[8][2]; };

__device__ __forceinline__ void fetch3(Frag3& f, uint32_t sA, uint32_t sB,
                                       int k16, int wm, int wn,
                                       int lrA, int lcA, int lrB, int lcB) {
    uint32_t hi = (uint32_t)(k16 >> 2) << 14;
    int kk = k16 & 3;
#pragma unroll
    for (int m = 0; m < 4; ++m) {
        int row = wm * 64 + m * 16 + lrA;
        uint32_t off = hi + ((uint32_t)row << 7) + ((uint32_t)((kk * 2 + lcA) ^ (row & 7)) << 4);
        ldsm4(f.a[m], sA + off);
    }
#pragma unroll
    for (int p = 0; p < 4; ++p) {
        int row = wn * 64 + p * 16 + lrB;
        uint32_t off = hi + ((uint32_t)row << 7) + ((uint32_t)((kk * 2 + lcB) ^ (row & 7)) << 4);
        uint32_t r4[4];
        ldsm4(r4, sB + off);
        f.b[2*p][0] = r4[0]; f.b[2*p][1] = r4[1]; f.b[2*p+1][0] = r4[2]; f.b[2*p+1][1] = r4[3];
    }
}

// stage layout: [A-lo 16K | A-hi 16K | B-lo 16K | B-hi 16K]; 128 loader threads
__device__ __forceinline__ void load_stage3(uint32_t sb, int tid, int k0,
                                            int row0, int bdrow) {
#pragma unroll
    for (int i = 0; i < 32; ++i) {
        int q = tid + (i << 7);               // 4096 chunks, 128 threads
        int half = q >> 11;                   // 0:A 1:B
        int q2 = q & 2047;
        int hi = q2 >> 10;                    // k-lo / k-hi sub-tile
        int q10 = q2 & 1023;
        int r = q10 >> 3, c = q10 & 7;
        uint32_t so = sb + ((uint32_t)half << 15) + ((uint32_t)hi << 14)
                    + (r << 7) + ((c ^ (r & 7)) << 4);
        const __half* base = half ? (g_Wd + (size_t)(bdrow + r) * FFD)
                                  : (g_H  + (size_t)(row0 + r) * FFD);
        cp16(so, base + k0 + (hi << 6) + (c << 3));
    }
    asm volatile("cp.async.commit_group;\n" ::: "memory");
}

__global__ void __launch_bounds__(128, 1)
gemm3_kernel(float* __restrict__ outp)
{
    int n0t = (g_cnt[0] + 127) >> 7, n1t = (g_cnt[1] + 127) >> 7;
    int tt = blockIdx.y;
    if (tt >= n0t + n1t) return;
    int expert = (tt < n0t) ? 0 : 1;
    int row0 = tt << 7;
    int col0 = blockIdx.x << 7;
    int bdrow = expert * DDim + col0;

    extern __shared__ char smem[];
    uint32_t sbase = (uint32_t)__cvta_generic_to_shared(smem);
    int tid = threadIdx.x, wid = tid >> 5, lane = tid & 31;
    int wm = wid & 1, wn = wid >> 1;          // 2x2 warps, 64x64 each

    int lrA = (lane & 7) + (((lane >> 3) & 1) << 3);
    int lcA = lane >> 4;
    int lrB = (lane & 7) + ((lane >> 4) << 3);
    int lcB = (lane >> 3) & 1;

    float acc[4][8][4];
#pragma unroll
    for (int m = 0; m < 4; ++m)
#pragma unroll
        for (int n = 0; n < 8; ++n)
#pragma unroll
            for (int i = 0; i < 4; ++i) acc[m][n][i] = 0.f;

    const int kTiles = FFD >> 7;              // 64
    load_stage3(sbase, tid, 0, row0, bdrow);
    Frag3 fr[2];

    for (int kt = 0; kt < kTiles; ++kt) {
        asm volatile("cp.async.wait_group 0;\n" ::: "memory");
        __syncthreads();
        uint32_t sb = sbase + (uint32_t)(kt & 1) * STAGE3;
        uint32_t sA = sb, sB = sb + 32768;

        fetch3(fr[0], sA, sB, 0, wm, wn, lrA, lcA, lrB, lcB);
        if (kt + 1 < kTiles)
            load_stage3(sbase + (uint32_t)((kt + 1) & 1) * STAGE3, tid,
                        (kt + 1) << 7, row0, bdrow);
#pragma unroll
        for (int k16 = 0; k16 < 8; ++k16) {
            int cur = k16 & 1;
            if (k16 < 7)
                fetch3(fr[cur ^ 1], sA, sB, k16 + 1, wm, wn, lrA, lcA, lrB, lcB);
#pragma unroll
            for (int m = 0; m < 4; ++m)
#pragma unroll
                for (int n = 0; n < 8; ++n)
                    mma_f16(acc[m][n], fr[cur].a[m], fr[cur].b[n]);
        }
    }

    // epilogue: scale by routing weight, streaming scatter to token rows
#pragma unroll
    for (int m = 0; m < 4; ++m) {
        int r0g = row0 + wm * 64 + m * 16 + (lane >> 2);
        int tok0 = g_tok[r0g];
        int tok1 = g_tok[r0g + 8];
        float w0 = (tok0 >= 0) ? g_topw[tok0] : 0.f;
        float w1 = (tok1 >= 0) ? g_topw[tok1] : 0.f;
#pragma unroll
        for (int n = 0; n < 8; ++n) {
            int gcol = col0 + wn * 64 + n * 8 + (lane & 3) * 2;
            if (tok0 >= 0) {
                float2 v; v.x = w0 * acc[m][n][0]; v.y = w0 * acc[m][n][1];
                __stcs((float2*)(outp + (size_t)tok0 * DDim + gcol), v);
            }
            if (tok1 >= 0) {
                float2 v; v.x = w1 * acc[m][n][2]; v.y = w1 * acc[m][n][3];
                __stcs((float2*)(outp + (size_t)tok1 * DDim + gcol), v);
            }
        }
    }
}

// ---------------- launch ----------------
extern "C" void kernel_launch(void* const* d_in, const int* in_sizes, int n_in,
                              void* d_out, int out_size)
{
    const float* x  = (const float*)d_in[0];
    const float* gw = (const float*)d_in[1];
    const float* wg = (const float*)d_in[2];
    const float* wu = (const float*)d_in[3];
    const float* wd = (const float*)d_in[4];
    float* out = (float*)d_out;

    static cudaStream_t s2 = nullptr;
    static cudaEvent_t evFork = nullptr, evGU = nullptr, evD = nullptr;
    if (s2 == nullptr) {
        cudaStreamCreateWithFlags(&s2, cudaStreamNonBlocking);
        cudaEventCreateWithFlags(&evFork, cudaEventDisableTiming);
        cudaEventCreateWithFlags(&evGU, cudaEventDisableTiming);
        cudaEventCreateWithFlags(&evD, cudaEventDisableTiming);
    }

    cudaFuncSetAttribute(gemm12_kernel, cudaFuncAttributeMaxDynamicSharedMemorySize, SMEM12);
    cudaFuncSetAttribute(gemm3_kernel,  cudaFuncAttributeMaxDynamicSharedMemorySize, SMEM3);

    cudaEventRecord(evFork, 0);
    cudaStreamWaitEvent(s2, evFork, 0);

    int wblocks16 = (int)(((size_t)NE * FFD * DDim / 16 + 511) / 512);
    wconv_gu_kernel<<<dim3(wblocks16, 2), 512, 0, s2>>>(wg, wu);
    cudaEventRecord(evGU, s2);
    wconv_d_kernel<<<wblocks16, 512, 0, s2>>>(wd);
    cudaEventRecord(evD, s2);

    init_kernel<<<(PADT + 255) / 256, 256>>>();
    router_kernel<<<(TT * 32) / 256, 256>>>(x, gw);
    assign_gather_kernel<<<(TT * 32) / 256, 256>>>(x);

    cudaStreamWaitEvent(0, evGU, 0);
    gemm12_kernel<<<dim3(NT, FFD / 128), 256, SMEM12>>>();

    cudaStreamWaitEvent(0, evD, 0);
    gemm3_kernel<<<dim3(DDim / 128, NT), 128, SMEM3>>>(out);
}

// round 16
// speedup vs baseline: 1.0065x; 1.0065x over previous
#include <cuda_runtime.h>
#include <cuda_fp16.h>
#include <stdint.h>

#define TT   8192
#define DDim 2048
#define FFD  8192
#define NE   2
#define PADT 8448      // 66*128
#define NT   66
#define STAGE12 98304  // [A-lo|A-hi|Bg-lo|Bg-hi|Bu-lo|Bu-hi] 6x16KB
#define STAGE3  65536  // [A-lo|A-hi|B-lo|B-hi] 4x16KB
#define SMEM12 (2*STAGE12)
#define SMEM3  (2*STAGE3)

// ---------------- scratch ----------------
__device__ __align__(256) __half g_Xh[(size_t)PADT*DDim];
__device__ __align__(256) __half g_Wg[(size_t)NE*FFD*DDim];
__device__ __align__(256) __half g_Wu[(size_t)NE*FFD*DDim];
__device__ __align__(256) __half g_Wd[(size_t)NE*DDim*FFD];
__device__ __align__(256) __half g_H[(size_t)PADT*FFD];
__device__ int   g_sel[TT];
__device__ float g_topw[TT];
__device__ int   g_tok[PADT];
__device__ int   g_cnt[2];
__device__ int   g_pos[2];

// ---------------- helpers ----------------
__device__ __forceinline__ void cp16(uint32_t saddr, const void* gaddr) {
    asm volatile("cp.async.cg.shared.global [%0], [%1], 16;\n"
                 :: "r"(saddr), "l"(gaddr) : "memory");
}
__device__ __forceinline__ void ldsm4(uint32_t* r, uint32_t addr) {
    asm volatile("ldmatrix.sync.aligned.m8n8.x4.shared.b16 {%0,%1,%2,%3}, [%4];\n"
                 : "=r"(r[0]), "=r"(r[1]), "=r"(r[2]), "=r"(r[3])
                 : "r"(addr) : "memory");
}
__device__ __forceinline__ void mma_f16(float* c, const uint32_t* a, const uint32_t* b) {
    asm volatile("mma.sync.aligned.m16n8k16.row.col.f32.f16.f16.f32 "
                 "{%0,%1,%2,%3}, {%4,%5,%6,%7}, {%8,%9}, {%0,%1,%2,%3};\n"
                 : "+f"(c[0]), "+f"(c[1]), "+f"(c[2]), "+f"(c[3])
                 : "r"(a[0]), "r"(a[1]), "r"(a[2]), "r"(a[3]),
                   "r"(b[0]), "r"(b[1]));
}
__device__ __forceinline__ uint32_t pack_h2(float a, float b) {
    __half2 h = __halves2half2(__float2half(a), __float2half(b));
    return *(uint32_t*)&h;
}

// ---------------- small kernels ----------------
__global__ void init_kernel() {
    int i = blockIdx.x * blockDim.x + threadIdx.x;
    if (i < PADT) g_tok[i] = -1;
    if (i == 0) { g_cnt[0] = 0; g_cnt[1] = 0; g_pos[0] = 0; g_pos[1] = 0; }
}

__global__ void router_kernel(const float* __restrict__ x, const float* __restrict__ gw) {
    int gt = blockIdx.x * blockDim.x + threadIdx.x;
    int t = gt >> 5, lane = gt & 31;
    if (t >= TT) return;
    const float* xr = x + (size_t)t * DDim;
    float a0 = 0.f, a1 = 0.f;
    for (int d = lane; d < DDim; d += 32) {
        float xv = xr[d];
        a0 += xv * gw[d];
        a1 += xv * gw[DDim + d];
    }
#pragma unroll
    for (int o = 16; o; o >>= 1) {
        a0 += __shfl_xor_sync(0xffffffffu, a0, o);
        a1 += __shfl_xor_sync(0xffffffffu, a1, o);
    }
    if (lane == 0) {
        int sel = (a0 >= a1) ? 0 : 1;
        float m = fmaxf(a0, a1);
        float e0 = expf(a0 - m), e1 = expf(a1 - m);
        float p = ((sel == 0) ? e0 : e1) / (e0 + e1);
        g_sel[t] = sel;
        g_topw[t] = p;
        atomicAdd(&g_cnt[sel], 1);
    }
}

__global__ void assign_gather_kernel(const float* __restrict__ x) {
    int gt = blockIdx.x * blockDim.x + threadIdx.x;
    int t = gt >> 5, lane = gt & 31;
    if (t >= TT) return;
    int slot = 0;
    if (lane == 0) {
        int sel = g_sel[t];
        int base = sel ? (((g_cnt[0] + 127) >> 7) << 7) : 0;
        int p = atomicAdd(&g_pos[sel], 1);
        slot = base + p;
        g_tok[slot] = t;
    }
    slot = __shfl_sync(0xffffffffu, slot, 0);
    const float4* xr = (const float4*)(x + (size_t)t * DDim);
    __half* dst = g_Xh + (size_t)slot * DDim;
#pragma unroll 4
    for (int c = lane; c < DDim / 4; c += 32) {
        float4 v = __ldcs(xr + c);
        uint2 o;
        o.x = pack_h2(v.x, v.y);
        o.y = pack_h2(v.z, v.w);
        *(uint2*)(dst + c * 4) = o;
    }
}

// streaming fp32->fp16 weight conversion — per-expert slab
__global__ void __launch_bounds__(512)
wconv_gu_kernel(const float* __restrict__ wg, const float* __restrict__ wu, int e) {
    const size_t half16 = (size_t)FFD * DDim / 16;
    size_t idx = (size_t)blockIdx.x * blockDim.x + threadIdx.x;
    if (idx >= half16) return;
    idx += (size_t)e * half16;
    const float* src = (blockIdx.y == 0) ? wg : wu;
    __half* dst = (blockIdx.y == 0) ? g_Wg : g_Wu;
    const float4* s4 = (const float4*)src + idx * 4;
    float4 v0 = __ldcs(s4);
    float4 v1 = __ldcs(s4 + 1);
    float4 v2 = __ldcs(s4 + 2);
    float4 v3 = __ldcs(s4 + 3);
    uint4 o0, o1;
    o0.x = pack_h2(v0.x, v0.y); o0.y = pack_h2(v0.z, v0.w);
    o0.z = pack_h2(v1.x, v1.y); o0.w = pack_h2(v1.z, v1.w);
    o1.x = pack_h2(v2.x, v2.y); o1.y = pack_h2(v2.z, v2.w);
    o1.z = pack_h2(v3.x, v3.y); o1.w = pack_h2(v3.z, v3.w);
    __stcs((uint4*)(dst + idx * 16), o0);
    __stcs((uint4*)(dst + idx * 16) + 1, o1);
}

__global__ void __launch_bounds__(512)
wconv_d_kernel(const float* __restrict__ wd) {
    const size_t n16 = (size_t)NE * FFD * DDim / 16;
    size_t idx = (size_t)blockIdx.x * blockDim.x + threadIdx.x;
    if (idx >= n16) return;
    const float4* s4 = (const float4*)wd + idx * 4;
    float4 v0 = __ldcs(s4);
    float4 v1 = __ldcs(s4 + 1);
    float4 v2 = __ldcs(s4 + 2);
    float4 v3 = __ldcs(s4 + 3);
    uint4 o0, o1;
    o0.x = pack_h2(v0.x, v0.y); o0.y = pack_h2(v0.z, v0.w);
    o0.z = pack_h2(v1.x, v1.y); o0.w = pack_h2(v1.z, v1.w);
    o1.x = pack_h2(v2.x, v2.y); o1.y = pack_h2(v2.z, v2.w);
    o1.z = pack_h2(v3.x, v3.y); o1.w = pack_h2(v3.z, v3.w);
    __stcs((uint4*)(g_Wd + idx * 16), o0);
    __stcs((uint4*)(g_Wd + idx * 16) + 1, o1);
}

// ============ fused gate+up GEMM: tile M128 x N128 x K128-slab (256 thr) ============
struct Frag12 { uint32_t a[4][4]; uint32_t g[4][2]; uint32_t u[4][2]; };

__device__ __forceinline__ void fetch12(Frag12& f, uint32_t sA, uint32_t sBg, uint32_t sBu,
                                        int k16, int wm, int wn,
                                        int lrA, int lcA, int lrB, int lcB) {
    uint32_t hi = (uint32_t)(k16 >> 2) << 14;
    int kk = k16 & 3;
#pragma unroll
    for (int m = 0; m < 4; ++m) {
        int row = wm * 64 + m * 16 + lrA;
        uint32_t off = hi + ((uint32_t)row << 7) + ((uint32_t)((kk * 2 + lcA) ^ (row & 7)) << 4);
        ldsm4(f.a[m], sA + off);
    }
#pragma unroll
    for (int p = 0; p < 2; ++p) {
        int row = wn * 32 + p * 16 + lrB;
        uint32_t off = hi + ((uint32_t)row << 7) + ((uint32_t)((kk * 2 + lcB) ^ (row & 7)) << 4);
        uint32_t r4[4];
        ldsm4(r4, sBg + off);
        f.g[2*p][0] = r4[0]; f.g[2*p][1] = r4[1]; f.g[2*p+1][0] = r4[2]; f.g[2*p+1][1] = r4[3];
        ldsm4(r4, sBu + off);
        f.u[2*p][0] = r4[0]; f.u[2*p][1] = r4[1]; f.u[2*p+1][0] = r4[2]; f.u[2*p+1][1] = r4[3];
    }
}

__device__ __forceinline__ void load_stage12(uint32_t sb, int tid, int k0,
                                             int row0, int bgrow) {
#pragma unroll
    for (int i = 0; i < 24; ++i) {
        int q = tid + (i << 8);
        int mat = q >> 10;
        int q10 = q & 1023;
        int r = q10 >> 3;
        int c = q10 & 7;
        uint32_t so = sb + ((uint32_t)mat << 14) + (r << 7) + ((c ^ (r & 7)) << 4);
        int kk = k0 + ((mat & 1) << 6) + (c << 3);
        int sel = mat >> 1;
        const __half* base = (sel == 0) ? (g_Xh + (size_t)(row0 + r) * DDim)
                           : (sel == 1) ? (g_Wg + (size_t)(bgrow + r) * DDim)
                                        : (g_Wu + (size_t)(bgrow + r) * DDim);
        cp16(so, base + kk);
    }
    asm volatile("cp.async.commit_group;\n" ::: "memory");
}

// expert-split: e=0 handles rows [0, n0t), e=1 handles [n0t, n0t+n1t)
__global__ void __launch_bounds__(256, 1)
gemm12_kernel(int e)
{
    int n0t = (g_cnt[0] + 127) >> 7, n1t = (g_cnt[1] + 127) >> 7;
    int tt = (e ? n0t : 0) + blockIdx.x;
    int lim = e ? (n0t + n1t) : n0t;
    if (tt >= lim) return;
    int row0 = tt << 7;
    int col0 = blockIdx.y << 7;
    int bgrow = e * FFD + col0;

    extern __shared__ char smem[];
    uint32_t sbase = (uint32_t)__cvta_generic_to_shared(smem);
    int tid = threadIdx.x, wid = tid >> 5, lane = tid & 31;
    int wm = wid & 1, wn = wid >> 1;

    int lrA = (lane & 7) + (((lane >> 3) & 1) << 3);
    int lcA = lane >> 4;
    int lrB = (lane & 7) + ((lane >> 4) << 3);
    int lcB = (lane >> 3) & 1;

    float ag[4][4][4], au[4][4][4];
#pragma unroll
    for (int m = 0; m < 4; ++m)
#pragma unroll
        for (int n = 0; n < 4; ++n)
#pragma unroll
            for (int i = 0; i < 4; ++i) { ag[m][n][i] = 0.f; au[m][n][i] = 0.f; }

    const int kTiles = DDim >> 7;             // 16
    load_stage12(sbase, tid, 0, row0, bgrow);
    Frag12 fr[2];

    for (int kt = 0; kt < kTiles; ++kt) {
        asm volatile("cp.async.wait_group 0;\n" ::: "memory");
        __syncthreads();
        uint32_t sb = sbase + (uint32_t)(kt & 1) * STAGE12;
        uint32_t sA = sb, sBg = sb + 32768, sBu = sb + 65536;

        fetch12(fr[0], sA, sBg, sBu, 0, wm, wn, lrA, lcA, lrB, lcB);
        if (kt + 1 < kTiles)
            load_stage12(sbase + (uint32_t)((kt + 1) & 1) * STAGE12, tid,
                         (kt + 1) << 7, row0, bgrow);
#pragma unroll
        for (int k16 = 0; k16 < 8; ++k16) {
            int cur = k16 & 1;
            if (k16 < 7)
                fetch12(fr[cur ^ 1], sA, sBg, sBu, k16 + 1, wm, wn, lrA, lcA, lrB, lcB);
#pragma unroll
            for (int m = 0; m < 4; ++m)
#pragma unroll
                for (int n = 0; n < 4; ++n) {
                    mma_f16(ag[m][n], fr[cur].a[m], fr[cur].g[n]);
                    mma_f16(au[m][n], fr[cur].a[m], fr[cur].u[n]);
                }
        }
    }

#pragma unroll
    for (int m = 0; m < 4; ++m) {
        int grow = row0 + wm * 64 + m * 16 + (lane >> 2);
#pragma unroll
        for (int n = 0; n < 4; ++n) {
            int gcol = col0 + wn * 32 + n * 8 + (lane & 3) * 2;
            float h0 = ag[m][n][0] * au[m][n][0] / (1.f + expf(-ag[m][n][0]));
            float h1 = ag[m][n][1] * au[m][n][1] / (1.f + expf(-ag[m][n][1]));
            float h2 = ag[m][n][2] * au[m][n][2] / (1.f + expf(-ag[m][n][2]));
            float h3 = ag[m][n][3] * au[m][n][3] / (1.f + expf(-ag[m][n][3]));
            *(uint32_t*)(g_H + (size_t)grow * FFD + gcol)       = pack_h2(h0, h1);
            *(uint32_t*)(g_H + (size_t)(grow + 8) * FFD + gcol) = pack_h2(h2, h3);
        }
    }
}

// ============ down GEMM: tile M128 x N128 x K128-slab, 256 threads ============
struct Frag3 { uint32_t a[4][4]; uint32_t b[4][2]; };

__device__ __forceinline__ void fetch3(Frag3& f, uint32_t sA, uint32_t sB,
                                       int k16, int wm, int wn,
                                       int lrA, int lcA, int lrB, int lcB) {
    uint32_t hi = (uint32_t)(k16 >> 2) << 14;
    int kk = k16 & 3;
#pragma unroll
    for (int m = 0; m < 4; ++m) {
        int row = wm * 64 + m * 16 + lrA;
        uint32_t off = hi + ((uint32_t)row << 7) + ((uint32_t)((kk * 2 + lcA) ^ (row & 7)) << 4);
        ldsm4(f.a[m], sA + off);
    }
#pragma unroll
    for (int p = 0; p < 2; ++p) {
        int row = wn * 32 + p * 16 + lrB;
        uint32_t off = hi + ((uint32_t)row << 7) + ((uint32_t)((kk * 2 + lcB) ^ (row & 7)) << 4);
        uint32_t r4[4];
        ldsm4(r4, sB + off);
        f.b[2*p][0] = r4[0]; f.b[2*p][1] = r4[1]; f.b[2*p+1][0] = r4[2]; f.b[2*p+1][1] = r4[3];
    }
}

__device__ __forceinline__ void load_stage3(uint32_t sb, int tid, int k0,
                                            int row0, int bdrow) {
#pragma unroll
    for (int i = 0; i < 16; ++i) {
        int q = tid + (i << 8);
        int half = q >> 11;
        int q2 = q & 2047;
        int hi = q2 >> 10;
        int q10 = q2 & 1023;
        int r = q10 >> 3, c = q10 & 7;
        uint32_t so = sb + ((uint32_t)half << 15) + ((uint32_t)hi << 14)
                    + (r << 7) + ((c ^ (r & 7)) << 4);
        const __half* base = half ? (g_Wd + (size_t)(bdrow + r) * FFD)
                                  : (g_H  + (size_t)(row0 + r) * FFD);
        cp16(so, base + k0 + (hi << 6) + (c << 3));
    }
    asm volatile("cp.async.commit_group;\n" ::: "memory");
}

__global__ void __launch_bounds__(256, 1)
gemm3_kernel(float* __restrict__ outp)
{
    int n0t = (g_cnt[0] + 127) >> 7, n1t = (g_cnt[1] + 127) >> 7;
    int tt = blockIdx.y;
    if (tt >= n0t + n1t) return;
    int expert = (tt < n0t) ? 0 : 1;
    int row0 = tt << 7;
    int col0 = blockIdx.x << 7;
    int bdrow = expert * DDim + col0;

    extern __shared__ char smem[];
    uint32_t sbase = (uint32_t)__cvta_generic_to_shared(smem);
    int tid = threadIdx.x, wid = tid >> 5, lane = tid & 31;
    int wm = wid & 1, wn = wid >> 1;

    int lrA = (lane & 7) + (((lane >> 3) & 1) << 3);
    int lcA = lane >> 4;
    int lrB = (lane & 7) + ((lane >> 4) << 3);
    int lcB = (lane >> 3) & 1;

    float acc[4][4][4];
#pragma unroll
    for (int m = 0; m < 4; ++m)
#pragma unroll
        for (int n = 0; n < 4; ++n)
#pragma unroll
            for (int i = 0; i < 4; ++i) acc[m][n][i] = 0.f;

    const int kTiles = FFD >> 7;              // 64
    load_stage3(sbase, tid, 0, row0, bdrow);
    Frag3 fr[2];

    for (int kt = 0; kt < kTiles; ++kt) {
        asm volatile("cp.async.wait_group 0;\n" ::: "memory");
        __syncthreads();
        uint32_t sb = sbase + (uint32_t)(kt & 1) * STAGE3;
        uint32_t sA = sb, sB = sb + 32768;

        fetch3(fr[0], sA, sB, 0, wm, wn, lrA, lcA, lrB, lcB);
        if (kt + 1 < kTiles)
            load_stage3(sbase + (uint32_t)((kt + 1) & 1) * STAGE3, tid,
                        (kt + 1) << 7, row0, bdrow);
#pragma unroll
        for (int k16 = 0; k16 < 8; ++k16) {
            int cur = k16 & 1;
            if (k16 < 7)
                fetch3(fr[cur ^ 1], sA, sB, k16 + 1, wm, wn, lrA, lcA, lrB, lcB);
#pragma unroll
            for (int m = 0; m < 4; ++m)
#pragma unroll
                for (int n = 0; n < 4; ++n)
                    mma_f16(acc[m][n], fr[cur].a[m], fr[cur].b[n]);
        }
    }

#pragma unroll
    for (int m = 0; m < 4; ++m) {
        int r0g = row0 + wm * 64 + m * 16 + (lane >> 2);
        int tok0 = g_tok[r0g];
        int tok1 = g_tok[r0g + 8];
        float w0 = (tok0 >= 0) ? g_topw[tok0] : 0.f;
        float w1 = (tok1 >= 0) ? g_topw[tok1] : 0.f;
#pragma unroll
        for (int n = 0; n < 4; ++n) {
            int gcol = col0 + wn * 32 + n * 8 + (lane & 3) * 2;
            if (tok0 >= 0) {
                float2 v; v.x = w0 * acc[m][n][0]; v.y = w0 * acc[m][n][1];
                __stcs((float2*)(outp + (size_t)tok0 * DDim + gcol), v);
            }
            if (tok1 >= 0) {
                float2 v; v.x = w1 * acc[m][n][2]; v.y = w1 * acc[m][n][3];
                __stcs((float2*)(outp + (size_t)tok1 * DDim + gcol), v);
            }
        }
    }
}

// ---------------- launch ----------------
extern "C" void kernel_launch(void* const* d_in, const int* in_sizes, int n_in,
                              void* d_out, int out_size)
{
    const float* x  = (const float*)d_in[0];
    const float* gw = (const float*)d_in[1];
    const float* wg = (const float*)d_in[2];
    const float* wu = (const float*)d_in[3];
    const float* wd = (const float*)d_in[4];
    float* out = (float*)d_out;

    static cudaStream_t s2 = nullptr, s3 = nullptr;
    static cudaEvent_t evFork = nullptr, evGU0 = nullptr, evGU1 = nullptr;
    static cudaEvent_t evD = nullptr, evRT = nullptr, evE1 = nullptr;
    if (s2 == nullptr) {
        cudaStreamCreateWithFlags(&s2, cudaStreamNonBlocking);
        cudaStreamCreateWithFlags(&s3, cudaStreamNonBlocking);
        cudaEventCreateWithFlags(&evFork, cudaEventDisableTiming);
        cudaEventCreateWithFlags(&evGU0, cudaEventDisableTiming);
        cudaEventCreateWithFlags(&evGU1, cudaEventDisableTiming);
        cudaEventCreateWithFlags(&evD, cudaEventDisableTiming);
        cudaEventCreateWithFlags(&evRT, cudaEventDisableTiming);
        cudaEventCreateWithFlags(&evE1, cudaEventDisableTiming);
    }

    cudaFuncSetAttribute(gemm12_kernel, cudaFuncAttributeMaxDynamicSharedMemorySize, SMEM12);
    cudaFuncSetAttribute(gemm3_kernel,  cudaFuncAttributeMaxDynamicSharedMemorySize, SMEM3);

    // fork weight conversion onto s2, expert-0 slab first
    cudaEventRecord(evFork, 0);
    cudaStreamWaitEvent(s2, evFork, 0);

    int wbHalf = (int)(((size_t)FFD * DDim / 16 + 511) / 512);
    wconv_gu_kernel<<<dim3(wbHalf, 2), 512, 0, s2>>>(wg, wu, 0);
    cudaEventRecord(evGU0, s2);
    wconv_gu_kernel<<<dim3(wbHalf, 2), 512, 0, s2>>>(wg, wu, 1);
    cudaEventRecord(evGU1, s2);
    int wblocks16 = (int)(((size_t)NE * FFD * DDim / 16 + 511) / 512);
    wconv_d_kernel<<<wblocks16, 512, 0, s2>>>(wd);
    cudaEventRecord(evD, s2);

    // main: router chain (parallel with wconv)
    init_kernel<<<(PADT + 255) / 256, 256>>>();
    router_kernel<<<(TT * 32) / 256, 256>>>(x, gw);
    assign_gather_kernel<<<(TT * 32) / 256, 256>>>(x);
    cudaEventRecord(evRT, 0);

    // expert-0 gemm12 on main: starts as soon as expert-0 weights + routing done
    cudaStreamWaitEvent(0, evGU0, 0);
    gemm12_kernel<<<dim3(NT - 1, FFD / 128), 256, SMEM12>>>(0);

    // expert-1 gemm12 on s3, concurrent with expert-0 (tails merge)
    cudaStreamWaitEvent(s3, evRT, 0);
    cudaStreamWaitEvent(s3, evGU1, 0);
    gemm12_kernel<<<dim3(NT - 1, FFD / 128), 256, SMEM12, s3>>>(1);
    cudaEventRecord(evE1, s3);

    // gemm3 after both gemm12 halves and Wd conversion
    cudaStreamWaitEvent(0, evE1, 0);
    cudaStreamWaitEvent(0, evD, 0);
    gemm3_kernel<<<dim3(DDim / 128, NT), 256, SMEM3>>>(out);
}

// round 17
// speedup vs baseline: 1.0111x; 1.0046x over previous
#include <cuda_runtime.h>
#include <cuda_fp16.h>
#include <stdint.h>

#define TT   8192
#define DDim 2048
#define FFD  8192
#define NE   2
#define PADT 8448      // 66*128
#define NT   66
#define STAGE12 98304  // [A-lo|A-hi|Bg-lo|Bg-hi|Bu-lo|Bu-hi] 6x16KB
#define STAGE3  65536  // [A-lo|A-hi|B-lo|B-hi] 4x16KB
#define SMEM12 (2*STAGE12)
#define SMEM3  (2*STAGE3)

// ---------------- scratch ----------------
__device__ __align__(256) __half g_Xh[(size_t)PADT*DDim];
__device__ __align__(256) __half g_Wg[(size_t)NE*FFD*DDim];
__device__ __align__(256) __half g_Wu[(size_t)NE*FFD*DDim];
__device__ __align__(256) __half g_Wd[(size_t)NE*DDim*FFD];
__device__ __align__(256) __half g_H[(size_t)PADT*FFD];
__device__ int   g_sel[TT];
__device__ float g_topw[TT];
__device__ int   g_tok[PADT];
__device__ int   g_cnt[2];
__device__ int   g_pos[2];

// ---------------- helpers ----------------
__device__ __forceinline__ void cp16(uint32_t saddr, const void* gaddr) {
    asm volatile("cp.async.cg.shared.global [%0], [%1], 16;\n"
                 :: "r"(saddr), "l"(gaddr) : "memory");
}
__device__ __forceinline__ void ldsm4(uint32_t* r, uint32_t addr) {
    asm volatile("ldmatrix.sync.aligned.m8n8.x4.shared.b16 {%0,%1,%2,%3}, [%4];\n"
                 : "=r"(r[0]), "=r"(r[1]), "=r"(r[2]), "=r"(r[3])
                 : "r"(addr) : "memory");
}
__device__ __forceinline__ void mma_f16(float* c, const uint32_t* a, const uint32_t* b) {
    asm volatile("mma.sync.aligned.m16n8k16.row.col.f32.f16.f16.f32 "
                 "{%0,%1,%2,%3}, {%4,%5,%6,%7}, {%8,%9}, {%0,%1,%2,%3};\n"
                 : "+f"(c[0]), "+f"(c[1]), "+f"(c[2]), "+f"(c[3])
                 : "r"(a[0]), "r"(a[1]), "r"(a[2]), "r"(a[3]),
                   "r"(b[0]), "r"(b[1]));
}
__device__ __forceinline__ uint32_t pack_h2(float a, float b) {
    __half2 h = __halves2half2(__float2half(a), __float2half(b));
    return *(uint32_t*)&h;
}

// ---------------- small kernels ----------------
__global__ void init_kernel() {
    int i = blockIdx.x * blockDim.x + threadIdx.x;
    if (i < PADT) g_tok[i] = -1;
    if (i == 0) { g_cnt[0] = 0; g_cnt[1] = 0; g_pos[0] = 0; g_pos[1] = 0; }
}

__global__ void router_kernel(const float* __restrict__ x, const float* __restrict__ gw) {
    int gt = blockIdx.x * blockDim.x + threadIdx.x;
    int t = gt >> 5, lane = gt & 31;
    if (t >= TT) return;
    const float* xr = x + (size_t)t * DDim;
    float a0 = 0.f, a1 = 0.f;
    for (int d = lane; d < DDim; d += 32) {
        float xv = xr[d];
        a0 += xv * gw[d];
        a1 += xv * gw[DDim + d];
    }
#pragma unroll
    for (int o = 16; o; o >>= 1) {
        a0 += __shfl_xor_sync(0xffffffffu, a0, o);
        a1 += __shfl_xor_sync(0xffffffffu, a1, o);
    }
    if (lane == 0) {
        int sel = (a0 >= a1) ? 0 : 1;
        float m = fmaxf(a0, a1);
        float e0 = expf(a0 - m), e1 = expf(a1 - m);
        float p = ((sel == 0) ? e0 : e1) / (e0 + e1);
        g_sel[t] = sel;
        g_topw[t] = p;
        atomicAdd(&g_cnt[sel], 1);
    }
}

__global__ void assign_gather_kernel(const float* __restrict__ x) {
    int gt = blockIdx.x * blockDim.x + threadIdx.x;
    int t = gt >> 5, lane = gt & 31;
    if (t >= TT) return;
    int slot = 0;
    if (lane == 0) {
        int sel = g_sel[t];
        int base = sel ? (((g_cnt[0] + 127) >> 7) << 7) : 0;
        int p = atomicAdd(&g_pos[sel], 1);
        slot = base + p;
        g_tok[slot] = t;
    }
    slot = __shfl_sync(0xffffffffu, slot, 0);
    const float4* xr = (const float4*)(x + (size_t)t * DDim);
    __half* dst = g_Xh + (size_t)slot * DDim;
#pragma unroll 4
    for (int c = lane; c < DDim / 4; c += 32) {
        float4 v = __ldcs(xr + c);
        uint2 o;
        o.x = pack_h2(v.x, v.y);
        o.y = pack_h2(v.z, v.w);
        *(uint2*)(dst + c * 4) = o;
    }
}

// streaming fp32->fp16 weight conversion — per-expert slab
__global__ void __launch_bounds__(512)
wconv_gu_kernel(const float* __restrict__ wg, const float* __restrict__ wu, int e) {
    const size_t half16 = (size_t)FFD * DDim / 16;
    size_t idx = (size_t)blockIdx.x * blockDim.x + threadIdx.x;
    if (idx >= half16) return;
    idx += (size_t)e * half16;
    const float* src = (blockIdx.y == 0) ? wg : wu;
    __half* dst = (blockIdx.y == 0) ? g_Wg : g_Wu;
    const float4* s4 = (const float4*)src + idx * 4;
    float4 v0 = __ldcs(s4);
    float4 v1 = __ldcs(s4 + 1);
    float4 v2 = __ldcs(s4 + 2);
    float4 v3 = __ldcs(s4 + 3);
    uint4 o0, o1;
    o0.x = pack_h2(v0.x, v0.y); o0.y = pack_h2(v0.z, v0.w);
    o0.z = pack_h2(v1.x, v1.y); o0.w = pack_h2(v1.z, v1.w);
    o1.x = pack_h2(v2.x, v2.y); o1.y = pack_h2(v2.z, v2.w);
    o1.z = pack_h2(v3.x, v3.y); o1.w = pack_h2(v3.z, v3.w);
    __stcs((uint4*)(dst + idx * 16), o0);
    __stcs((uint4*)(dst + idx * 16) + 1, o1);
}

__global__ void __launch_bounds__(512)
wconv_d_kernel(const float* __restrict__ wd) {
    const size_t n16 = (size_t)NE * FFD * DDim / 16;
    size_t idx = (size_t)blockIdx.x * blockDim.x + threadIdx.x;
    if (idx >= n16) return;
    const float4* s4 = (const float4*)wd + idx * 4;
    float4 v0 = __ldcs(s4);
    float4 v1 = __ldcs(s4 + 1);
    float4 v2 = __ldcs(s4 + 2);
    float4 v3 = __ldcs(s4 + 3);
    uint4 o0, o1;
    o0.x = pack_h2(v0.x, v0.y); o0.y = pack_h2(v0.z, v0.w);
    o0.z = pack_h2(v1.x, v1.y); o0.w = pack_h2(v1.z, v1.w);
    o1.x = pack_h2(v2.x, v2.y); o1.y = pack_h2(v2.z, v2.w);
    o1.z = pack_h2(v3.x, v3.y); o1.w = pack_h2(v3.z, v3.w);
    __stcs((uint4*)(g_Wd + idx * 16), o0);
    __stcs((uint4*)(g_Wd + idx * 16) + 1, o1);
}

// ============ fused gate+up GEMM: tile M128 x N128 x K128-slab (256 thr) ============
struct Frag12 { uint32_t a[4][4]; uint32_t g[4][2]; uint32_t u[4][2]; };

__device__ __forceinline__ void fetch12(Frag12& f, uint32_t sA, uint32_t sBg, uint32_t sBu,
                                        int k16, int wm, int wn,
                                        int lrA, int lcA, int lrB, int lcB) {
    uint32_t hi = (uint32_t)(k16 >> 2) << 14;
    int kk = k16 & 3;
#pragma unroll
    for (int m = 0; m < 4; ++m) {
        int row = wm * 64 + m * 16 + lrA;
        uint32_t off = hi + ((uint32_t)row << 7) + ((uint32_t)((kk * 2 + lcA) ^ (row & 7)) << 4);
        ldsm4(f.a[m], sA + off);
    }
#pragma unroll
    for (int p = 0; p < 2; ++p) {
        int row = wn * 32 + p * 16 + lrB;
        uint32_t off = hi + ((uint32_t)row << 7) + ((uint32_t)((kk * 2 + lcB) ^ (row & 7)) << 4);
        uint32_t r4[4];
        ldsm4(r4, sBg + off);
        f.g[2*p][0] = r4[0]; f.g[2*p][1] = r4[1]; f.g[2*p+1][0] = r4[2]; f.g[2*p+1][1] = r4[3];
        ldsm4(r4, sBu + off);
        f.u[2*p][0] = r4[0]; f.u[2*p][1] = r4[1]; f.u[2*p+1][0] = r4[2]; f.u[2*p+1][1] = r4[3];
    }
}

__device__ __forceinline__ void load_stage12(uint32_t sb, int tid, int k0,
                                             int row0, int bgrow) {
#pragma unroll
    for (int i = 0; i < 24; ++i) {
        int q = tid + (i << 8);
        int mat = q >> 10;
        int q10 = q & 1023;
        int r = q10 >> 3;
        int c = q10 & 7;
        uint32_t so = sb + ((uint32_t)mat << 14) + (r << 7) + ((c ^ (r & 7)) << 4);
        int kk = k0 + ((mat & 1) << 6) + (c << 3);
        int sel = mat >> 1;
        const __half* base = (sel == 0) ? (g_Xh + (size_t)(row0 + r) * DDim)
                           : (sel == 1) ? (g_Wg + (size_t)(bgrow + r) * DDim)
                                        : (g_Wu + (size_t)(bgrow + r) * DDim);
        cp16(so, base + kk);
    }
    asm volatile("cp.async.commit_group;\n" ::: "memory");
}

// expert-split: e=0 handles rows [0, n0t), e=1 handles [n0t, n0t+n1t)
__global__ void __launch_bounds__(256, 1)
gemm12_kernel(int e)
{
    int n0t = (g_cnt[0] + 127) >> 7, n1t = (g_cnt[1] + 127) >> 7;
    int tt = (e ? n0t : 0) + blockIdx.x;
    int lim = e ? (n0t + n1t) : n0t;
    if (tt >= lim) return;
    int row0 = tt << 7;
    int col0 = blockIdx.y << 7;
    int bgrow = e * FFD + col0;

    extern __shared__ char smem[];
    uint32_t sbase = (uint32_t)__cvta_generic_to_shared(smem);
    int tid = threadIdx.x, wid = tid >> 5, lane = tid & 31;
    int wm = wid & 1, wn = wid >> 1;

    int lrA = (lane & 7) + (((lane >> 3) & 1) << 3);
    int lcA = lane >> 4;
    int lrB = (lane & 7) + ((lane >> 4) << 3);
    int lcB = (lane >> 3) & 1;

    float ag[4][4][4], au[4][4][4];
#pragma unroll
    for (int m = 0; m < 4; ++m)
#pragma unroll
        for (int n = 0; n < 4; ++n)
#pragma unroll
            for (int i = 0; i < 4; ++i) { ag[m][n][i] = 0.f; au[m][n][i] = 0.f; }

    const int kTiles = DDim >> 7;             // 16
    load_stage12(sbase, tid, 0, row0, bgrow);
    Frag12 fr[2];

    for (int kt = 0; kt < kTiles; ++kt) {
        asm volatile("cp.async.wait_group 0;\n" ::: "memory");
        __syncthreads();
        uint32_t sb = sbase + (uint32_t)(kt & 1) * STAGE12;
        uint32_t sA = sb, sBg = sb + 32768, sBu = sb + 65536;

        fetch12(fr[0], sA, sBg, sBu, 0, wm, wn, lrA, lcA, lrB, lcB);
        if (kt + 1 < kTiles)
            load_stage12(sbase + (uint32_t)((kt + 1) & 1) * STAGE12, tid,
                         (kt + 1) << 7, row0, bgrow);
#pragma unroll
        for (int k16 = 0; k16 < 8; ++k16) {
            int cur = k16 & 1;
            if (k16 < 7)
                fetch12(fr[cur ^ 1], sA, sBg, sBu, k16 + 1, wm, wn, lrA, lcA, lrB, lcB);
#pragma unroll
            for (int m = 0; m < 4; ++m)
#pragma unroll
                for (int n = 0; n < 4; ++n) {
                    mma_f16(ag[m][n], fr[cur].a[m], fr[cur].g[n]);
                    mma_f16(au[m][n], fr[cur].a[m], fr[cur].u[n]);
                }
        }
    }

#pragma unroll
    for (int m = 0; m < 4; ++m) {
        int grow = row0 + wm * 64 + m * 16 + (lane >> 2);
#pragma unroll
        for (int n = 0; n < 4; ++n) {
            int gcol = col0 + wn * 32 + n * 8 + (lane & 3) * 2;
            float h0 = ag[m][n][0] * au[m][n][0] / (1.f + expf(-ag[m][n][0]));
            float h1 = ag[m][n][1] * au[m][n][1] / (1.f + expf(-ag[m][n][1]));
            float h2 = ag[m][n][2] * au[m][n][2] / (1.f + expf(-ag[m][n][2]));
            float h3 = ag[m][n][3] * au[m][n][3] / (1.f + expf(-ag[m][n][3]));
            *(uint32_t*)(g_H + (size_t)grow * FFD + gcol)       = pack_h2(h0, h1);
            *(uint32_t*)(g_H + (size_t)(grow + 8) * FFD + gcol) = pack_h2(h2, h3);
        }
    }
}

// ============ down GEMM: tile M128 x N128 x K128-slab, 256 thr, expert-split ============
struct Frag3 { uint32_t a[4][4]; uint32_t b[4][2]; };

__device__ __forceinline__ void fetch3(Frag3& f, uint32_t sA, uint32_t sB,
                                       int k16, int wm, int wn,
                                       int lrA, int lcA, int lrB, int lcB) {
    uint32_t hi = (uint32_t)(k16 >> 2) << 14;
    int kk = k16 & 3;
#pragma unroll
    for (int m = 0; m < 4; ++m) {
        int row = wm * 64 + m * 16 + lrA;
        uint32_t off = hi + ((uint32_t)row << 7) + ((uint32_t)((kk * 2 + lcA) ^ (row & 7)) << 4);
        ldsm4(f.a[m], sA + off);
    }
#pragma unroll
    for (int p = 0; p < 2; ++p) {
        int row = wn * 32 + p * 16 + lrB;
        uint32_t off = hi + ((uint32_t)row << 7) + ((uint32_t)((kk * 2 + lcB) ^ (row & 7)) << 4);
        uint32_t r4[4];
        ldsm4(r4, sB + off);
        f.b[2*p][0] = r4[0]; f.b[2*p][1] = r4[1]; f.b[2*p+1][0] = r4[2]; f.b[2*p+1][1] = r4[3];
    }
}

__device__ __forceinline__ void load_stage3(uint32_t sb, int tid, int k0,
                                            int row0, int bdrow) {
#pragma unroll
    for (int i = 0; i < 16; ++i) {
        int q = tid + (i << 8);
        int half = q >> 11;
        int q2 = q & 2047;
        int hi = q2 >> 10;
        int q10 = q2 & 1023;
        int r = q10 >> 3, c = q10 & 7;
        uint32_t so = sb + ((uint32_t)half << 15) + ((uint32_t)hi << 14)
                    + (r << 7) + ((c ^ (r & 7)) << 4);
        const __half* base = half ? (g_Wd + (size_t)(bdrow + r) * FFD)
                                  : (g_H  + (size_t)(row0 + r) * FFD);
        cp16(so, base + k0 + (hi << 6) + (c << 3));
    }
    asm volatile("cp.async.commit_group;\n" ::: "memory");
}

__global__ void __launch_bounds__(256, 1)
gemm3_kernel(int e, float* __restrict__ outp)
{
    int n0t = (g_cnt[0] + 127) >> 7, n1t = (g_cnt[1] + 127) >> 7;
    int tt = (e ? n0t : 0) + blockIdx.y;
    int lim = e ? (n0t + n1t) : n0t;
    if (tt >= lim) return;
    int row0 = tt << 7;
    int col0 = blockIdx.x << 7;
    int bdrow = e * DDim + col0;

    extern __shared__ char smem[];
    uint32_t sbase = (uint32_t)__cvta_generic_to_shared(smem);
    int tid = threadIdx.x, wid = tid >> 5, lane = tid & 31;
    int wm = wid & 1, wn = wid >> 1;

    int lrA = (lane & 7) + (((lane >> 3) & 1) << 3);
    int lcA = lane >> 4;
    int lrB = (lane & 7) + ((lane >> 4) << 3);
    int lcB = (lane >> 3) & 1;

    float acc[4][4][4];
#pragma unroll
    for (int m = 0; m < 4; ++m)
#pragma unroll
        for (int n = 0; n < 4; ++n)
#pragma unroll
            for (int i = 0; i < 4; ++i) acc[m][n][i] = 0.f;

    const int kTiles = FFD >> 7;              // 64
    load_stage3(sbase, tid, 0, row0, bdrow);
    Frag3 fr[2];

    for (int kt = 0; kt < kTiles; ++kt) {
        asm volatile("cp.async.wait_group 0;\n" ::: "memory");
        __syncthreads();
        uint32_t sb = sbase + (uint32_t)(kt & 1) * STAGE3;
        uint32_t sA = sb, sB = sb + 32768;

        fetch3(fr[0], sA, sB, 0, wm, wn, lrA, lcA, lrB, lcB);
        if (kt + 1 < kTiles)
            load_stage3(sbase + (uint32_t)((kt + 1) & 1) * STAGE3, tid,
                        (kt + 1) << 7, row0, bdrow);
#pragma unroll
        for (int k16 = 0; k16 < 8; ++k16) {
            int cur = k16 & 1;
            if (k16 < 7)
                fetch3(fr[cur ^ 1], sA, sB, k16 + 1, wm, wn, lrA, lcA, lrB, lcB);
#pragma unroll
            for (int m = 0; m < 4; ++m)
#pragma unroll
                for (int n = 0; n < 4; ++n)
                    mma_f16(acc[m][n], fr[cur].a[m], fr[cur].b[n]);
        }
    }

#pragma unroll
    for (int m = 0; m < 4; ++m) {
        int r0g = row0 + wm * 64 + m * 16 + (lane >> 2);
        int tok0 = g_tok[r0g];
        int tok1 = g_tok[r0g + 8];
        float w0 = (tok0 >= 0) ? g_topw[tok0] : 0.f;
        float w1 = (tok1 >= 0) ? g_topw[tok1] : 0.f;
#pragma unroll
        for (int n = 0; n < 4; ++n) {
            int gcol = col0 + wn * 32 + n * 8 + (lane & 3) * 2;
            if (tok0 >= 0) {
                float2 v; v.x = w0 * acc[m][n][0]; v.y = w0 * acc[m][n][1];
                __stcs((float2*)(outp + (size_t)tok0 * DDim + gcol), v);
            }
            if (tok1 >= 0) {
                float2 v; v.x = w1 * acc[m][n][2]; v.y = w1 * acc[m][n][3];
                __stcs((float2*)(outp + (size_t)tok1 * DDim + gcol), v);
            }
        }
    }
}

// ---------------- launch ----------------
extern "C" void kernel_launch(void* const* d_in, const int* in_sizes, int n_in,
                              void* d_out, int out_size)
{
    const float* x  = (const float*)d_in[0];
    const float* gw = (const float*)d_in[1];
    const float* wg = (const float*)d_in[2];
    const float* wu = (const float*)d_in[3];
    const float* wd = (const float*)d_in[4];
    float* out = (float*)d_out;

    static cudaStream_t s2 = nullptr, s3 = nullptr;
    static cudaEvent_t evFork = nullptr, evGU0 = nullptr, evGU1 = nullptr;
    static cudaEvent_t evD = nullptr, evRT = nullptr, evE3 = nullptr;
    if (s2 == nullptr) {
        cudaStreamCreateWithFlags(&s2, cudaStreamNonBlocking);
        cudaStreamCreateWithFlags(&s3, cudaStreamNonBlocking);
        cudaEventCreateWithFlags(&evFork, cudaEventDisableTiming);
        cudaEventCreateWithFlags(&evGU0, cudaEventDisableTiming);
        cudaEventCreateWithFlags(&evGU1, cudaEventDisableTiming);
        cudaEventCreateWithFlags(&evD, cudaEventDisableTiming);
        cudaEventCreateWithFlags(&evRT, cudaEventDisableTiming);
        cudaEventCreateWithFlags(&evE3, cudaEventDisableTiming);
    }

    cudaFuncSetAttribute(gemm12_kernel, cudaFuncAttributeMaxDynamicSharedMemorySize, SMEM12);
    cudaFuncSetAttribute(gemm3_kernel,  cudaFuncAttributeMaxDynamicSharedMemorySize, SMEM3);

    // fork weight conversion onto s2, expert-0 slab first
    cudaEventRecord(evFork, 0);
    cudaStreamWaitEvent(s2, evFork, 0);

    int wbHalf = (int)(((size_t)FFD * DDim / 16 + 511) / 512);
    wconv_gu_kernel<<<dim3(wbHalf, 2), 512, 0, s2>>>(wg, wu, 0);
    cudaEventRecord(evGU0, s2);
    wconv_gu_kernel<<<dim3(wbHalf, 2), 512, 0, s2>>>(wg, wu, 1);
    cudaEventRecord(evGU1, s2);
    int wblocks16 = (int)(((size_t)NE * FFD * DDim / 16 + 511) / 512);
    wconv_d_kernel<<<wblocks16, 512, 0, s2>>>(wd);
    cudaEventRecord(evD, s2);

    // main: router chain (parallel with wconv)
    init_kernel<<<(PADT + 255) / 256, 256>>>();
    router_kernel<<<(TT * 32) / 256, 256>>>(x, gw);
    assign_gather_kernel<<<(TT * 32) / 256, 256>>>(x);
    cudaEventRecord(evRT, 0);

    // expert-0 chain on main: gemm12(e0) -> gemm3(e0)
    cudaStreamWaitEvent(0, evGU0, 0);
    gemm12_kernel<<<dim3(NT - 1, FFD / 128), 256, SMEM12>>>(0);
    cudaStreamWaitEvent(0, evD, 0);
    gemm3_kernel<<<dim3(DDim / 128, NT - 1), 256, SMEM3>>>(0, out);

    // expert-1 chain on s3: gemm12(e1) -> gemm3(e1), concurrent with expert-0
    cudaStreamWaitEvent(s3, evRT, 0);
    cudaStreamWaitEvent(s3, evGU1, 0);
    gemm12_kernel<<<dim3(NT - 1, FFD / 128), 256, SMEM12, s3>>>(1);
    cudaStreamWaitEvent(s3, evD, 0);
    gemm3_kernel<<<dim3(DDim / 128, NT - 1), 256, SMEM3, s3>>>(1, out);
    cudaEventRecord(evE3, s3);

    // join: main's last node depends on the expert-1 chain
    cudaStreamWaitEvent(0, evE3, 0);
}